// round 1
// baseline (speedup 1.0000x reference)
#include <cuda_runtime.h>
#include <math.h>

#define BATCH 2
#define CIN   256
#define NPIX  6400
#define CK    64
#define CV    128
#define CO    256

// Scratch (device globals: allocation-free)
__device__ float g_Q[BATCH*NPIX*CK];    // [b][n][ck]  (pre-scaled by Ck^-0.5)
__device__ float g_K[BATCH*NPIX*CK];    // [b][n][ck]
__device__ float g_V[BATCH*NPIX*CV];    // [b][n][cv]
__device__ float g_CTX[BATCH*NPIX*CV];  // [b][n][cv]

// ---------------------------------------------------------------------------
// Projection: out[b][n][o] = (sum_c W[o][c]*X[b][c][n]) * scale[o] + bias2[o]
// BN mode: scale = g*rsqrt(v+eps), bias2 = b - m*scale ; else scale=1, bias2=b
// outmul folds the attention 1/sqrt(Ck) into q.
// ---------------------------------------------------------------------------
template<int COP, bool BN>
__global__ __launch_bounds__(256) void proj_kernel(
    const float* __restrict__ xin, const float* __restrict__ w,
    const float* __restrict__ pg,  const float* __restrict__ pb,
    const float* __restrict__ pm,  const float* __restrict__ pv,
    float* __restrict__ outp, float outmul)
{
    constexpr int R = COP / 16;           // outputs per thread (4 or 8)
    __shared__ float Xs[32][64];
    __shared__ float Wst[32][COP];
    const int n0  = blockIdx.x * 64;
    const int b   = blockIdx.y;
    const int tid = threadIdx.x;
    const int tx  = tid & 15, ty = tid >> 4;

    float acc[R][4];
#pragma unroll
    for (int r = 0; r < R; r++)
#pragma unroll
        for (int i = 0; i < 4; i++) acc[r][i] = 0.f;

    const float* xb = xin + (size_t)b * CIN * NPIX + n0;
    for (int cc = 0; cc < CIN; cc += 32) {
        for (int idx = tid; idx < 512; idx += 256) {
            int c = idx >> 4, nf = idx & 15;
            *(float4*)&Xs[c][nf*4] =
                *(const float4*)(xb + (size_t)(cc + c) * NPIX + nf*4);
        }
        for (int idx = tid; idx < COP*8; idx += 256) {
            int o = idx % COP, cf = idx / COP;
            float4 wv = *(const float4*)(w + (size_t)o * CIN + cc + cf*4);
            Wst[cf*4+0][o] = wv.x; Wst[cf*4+1][o] = wv.y;
            Wst[cf*4+2][o] = wv.z; Wst[cf*4+3][o] = wv.w;
        }
        __syncthreads();
#pragma unroll
        for (int c = 0; c < 32; c++) {
            float4 av = *(const float4*)&Xs[c][tx*4];
            float wr[R];
#pragma unroll
            for (int r = 0; r < R; r++) wr[r] = Wst[c][ty*R + r];
#pragma unroll
            for (int r = 0; r < R; r++) {
                acc[r][0] = fmaf(wr[r], av.x, acc[r][0]);
                acc[r][1] = fmaf(wr[r], av.y, acc[r][1]);
                acc[r][2] = fmaf(wr[r], av.z, acc[r][2]);
                acc[r][3] = fmaf(wr[r], av.w, acc[r][3]);
            }
        }
        __syncthreads();
    }

    float sc[R], b2[R];
#pragma unroll
    for (int r = 0; r < R; r++) {
        int o = ty*R + r;
        if constexpr (BN) {
            float s = pg[o] * rsqrtf(pv[o] + 1e-5f);
            sc[r] = s * outmul; b2[r] = (pb[o] - pm[o]*s) * outmul;
        } else {
            sc[r] = outmul; b2[r] = pb[o] * outmul;
        }
    }
    float* ob = outp + ((size_t)b * NPIX + n0) * COP + ty*R;
#pragma unroll
    for (int i = 0; i < 4; i++) {
#pragma unroll
        for (int r = 0; r < R; r += 4) {
            float4 v4;
            v4.x = acc[r+0][i]*sc[r+0] + b2[r+0];
            v4.y = acc[r+1][i]*sc[r+1] + b2[r+1];
            v4.z = acc[r+2][i]*sc[r+2] + b2[r+2];
            v4.w = acc[r+3][i]*sc[r+3] + b2[r+3];
            *(float4*)(ob + (size_t)(tx*4 + i) * COP + r) = v4;
        }
    }
}

// ---------------------------------------------------------------------------
// Flash attention: BM=32 queries per CTA, key tiles of 64, online softmax.
// ctx[b][n][v] = sum_m softmax_m(q[n].k[m]) * v_feat[m][v]
// ---------------------------------------------------------------------------
#define ATTN_SMEM_FLOATS (2048 + 4096 + 2112 + 8192)   // Qs + Ks + Ps + Vs

__global__ __launch_bounds__(256) void attn_kernel(
    const float* __restrict__ gQ, const float* __restrict__ gK,
    const float* __restrict__ gV, float* __restrict__ gC)
{
    extern __shared__ float sm[];
    float (*Qs)[32]  = (float(*)[32]) sm;                       // [k=64][i=32]
    float (*Ks)[64]  = (float(*)[64])(sm + 2048);               // [k=64][j=64]
    float (*Ps)[33]  = (float(*)[33])(sm + 2048 + 4096);        // [j=64][i=32+1]
    float (*Vs)[128] = (float(*)[128])(sm + 2048 + 4096 + 2112);// [j=64][v=128]

    const int n0  = blockIdx.x * 32;
    const int b   = blockIdx.y;
    const int tid = threadIdx.x;
    const int tx  = tid & 15, ty = tid >> 4;

    // Load Q tile transposed (k-major)
    const size_t qbase = ((size_t)b * NPIX + n0) * CK;
    for (int idx = tid; idx < 512; idx += 256) {
        int i = idx & 31, kf = idx >> 5;
        float4 q4 = *(const float4*)(gQ + qbase + (size_t)i * CK + kf*4);
        Qs[kf*4+0][i] = q4.x; Qs[kf*4+1][i] = q4.y;
        Qs[kf*4+2][i] = q4.z; Qs[kf*4+3][i] = q4.w;
    }

    float m_r[2] = {-1e30f, -1e30f};
    float l_r[2] = {0.f, 0.f};
    float oa[2][8];
#pragma unroll
    for (int r = 0; r < 2; r++)
#pragma unroll
        for (int c = 0; c < 8; c++) oa[r][c] = 0.f;

    for (int m0 = 0; m0 < NPIX; m0 += 64) {
        __syncthreads();   // previous iter's PV reads done (also covers Q load)
        const size_t kb = ((size_t)b * NPIX + m0);
        // K tile transposed; 32B-coherent global reads
        for (int idx = tid; idx < 1024; idx += 256) {
            int j = (idx >> 2) & 63; int ch = (idx >> 8) * 4 + (idx & 3);
            float4 k4 = *(const float4*)(gK + (kb + j) * CK + ch*4);
            Ks[ch*4+0][j] = k4.x; Ks[ch*4+1][j] = k4.y;
            Ks[ch*4+2][j] = k4.z; Ks[ch*4+3][j] = k4.w;
        }
        // V tile direct (fully coalesced)
        for (int idx = tid; idx < 2048; idx += 256) {
            int j = idx >> 5, vf = idx & 31;
            *(float4*)&Vs[j][vf*4] = *(const float4*)(gV + (kb + j) * CV + vf*4);
        }
        __syncthreads();

        // S = Q^T K  (q already carries 1/sqrt(Ck))
        float s0[4] = {0,0,0,0}, s1[4] = {0,0,0,0};
#pragma unroll 8
        for (int k = 0; k < 64; k++) {
            float2 qa = *(const float2*)&Qs[k][ty*2];
            float4 kv = *(const float4*)&Ks[k][tx*4];
            s0[0] = fmaf(qa.x, kv.x, s0[0]); s0[1] = fmaf(qa.x, kv.y, s0[1]);
            s0[2] = fmaf(qa.x, kv.z, s0[2]); s0[3] = fmaf(qa.x, kv.w, s0[3]);
            s1[0] = fmaf(qa.y, kv.x, s1[0]); s1[1] = fmaf(qa.y, kv.y, s1[1]);
            s1[2] = fmaf(qa.y, kv.z, s1[2]); s1[3] = fmaf(qa.y, kv.w, s1[3]);
        }

        // online softmax per owned row (reduce across the 16 tx lanes)
#pragma unroll
        for (int r = 0; r < 2; r++) {
            float* s = (r == 0) ? s0 : s1;
            float mx = fmaxf(fmaxf(s[0], s[1]), fmaxf(s[2], s[3]));
#pragma unroll
            for (int off = 8; off >= 1; off >>= 1)
                mx = fmaxf(mx, __shfl_xor_sync(0xffffffffu, mx, off));
            float mnew  = fmaxf(m_r[r], mx);
            float alpha = __expf(m_r[r] - mnew);
            float ls = 0.f;
#pragma unroll
            for (int c = 0; c < 4; c++) { s[c] = __expf(s[c] - mnew); ls += s[c]; }
#pragma unroll
            for (int off = 8; off >= 1; off >>= 1)
                ls += __shfl_xor_sync(0xffffffffu, ls, off);
            l_r[r] = l_r[r] * alpha + ls;
            m_r[r] = mnew;
#pragma unroll
            for (int c = 0; c < 8; c++) oa[r][c] *= alpha;
#pragma unroll
            for (int c = 0; c < 4; c++) Ps[tx*4 + c][ty*2 + r] = s[c];
        }
        __syncthreads();

        // O += P V
#pragma unroll 4
        for (int j = 0; j < 64; j++) {
            float p0 = Ps[j][ty*2 + 0], p1 = Ps[j][ty*2 + 1];
            float4 v0 = *(const float4*)&Vs[j][tx*8];
            float4 v1 = *(const float4*)&Vs[j][tx*8 + 4];
            oa[0][0] = fmaf(p0, v0.x, oa[0][0]); oa[0][1] = fmaf(p0, v0.y, oa[0][1]);
            oa[0][2] = fmaf(p0, v0.z, oa[0][2]); oa[0][3] = fmaf(p0, v0.w, oa[0][3]);
            oa[0][4] = fmaf(p0, v1.x, oa[0][4]); oa[0][5] = fmaf(p0, v1.y, oa[0][5]);
            oa[0][6] = fmaf(p0, v1.z, oa[0][6]); oa[0][7] = fmaf(p0, v1.w, oa[0][7]);
            oa[1][0] = fmaf(p1, v0.x, oa[1][0]); oa[1][1] = fmaf(p1, v0.y, oa[1][1]);
            oa[1][2] = fmaf(p1, v0.z, oa[1][2]); oa[1][3] = fmaf(p1, v0.w, oa[1][3]);
            oa[1][4] = fmaf(p1, v1.x, oa[1][4]); oa[1][5] = fmaf(p1, v1.y, oa[1][5]);
            oa[1][6] = fmaf(p1, v1.z, oa[1][6]); oa[1][7] = fmaf(p1, v1.w, oa[1][7]);
        }
    }

    const size_t ob = ((size_t)b * NPIX + n0) * CV;
#pragma unroll
    for (int r = 0; r < 2; r++) {
        float inv = 1.f / l_r[r];
        float4 w0, w1;
        w0.x = oa[r][0]*inv; w0.y = oa[r][1]*inv; w0.z = oa[r][2]*inv; w0.w = oa[r][3]*inv;
        w1.x = oa[r][4]*inv; w1.y = oa[r][5]*inv; w1.z = oa[r][6]*inv; w1.w = oa[r][7]*inv;
        *(float4*)(gC + ob + (size_t)(ty*2 + r) * CV + tx*8)     = w0;
        *(float4*)(gC + ob + (size_t)(ty*2 + r) * CV + tx*8 + 4) = w1;
    }
}

// ---------------------------------------------------------------------------
// Output projection + residual: out[b][o][n] = gamma*(Ww[o].ctx[n] + Wb[o]) + x
// ---------------------------------------------------------------------------
__global__ __launch_bounds__(256) void outproj_kernel(
    const float* __restrict__ Ww, const float* __restrict__ Wb,
    const float* __restrict__ xin, const float* __restrict__ gamma,
    const float* __restrict__ gC, float* __restrict__ outp)
{
    __shared__ float Wst[32][64];
    __shared__ float Cts[32][64];
    const int n0 = blockIdx.x * 64;
    const int o0 = blockIdx.y * 64;
    const int b  = blockIdx.z;
    const int tid = threadIdx.x;
    const int tx  = tid & 15, ty = tid >> 4;

    float acc[4][4];
#pragma unroll
    for (int r = 0; r < 4; r++)
#pragma unroll
        for (int i = 0; i < 4; i++) acc[r][i] = 0.f;

    for (int vc = 0; vc < CV; vc += 32) {
        for (int idx = tid; idx < 512; idx += 256) {
            int o = idx & 63, vf = idx >> 6;
            float4 wv = *(const float4*)(Ww + (size_t)(o0 + o) * CV + vc + vf*4);
            Wst[vf*4+0][o] = wv.x; Wst[vf*4+1][o] = wv.y;
            Wst[vf*4+2][o] = wv.z; Wst[vf*4+3][o] = wv.w;
        }
        for (int idx = tid; idx < 512; idx += 256) {
            int n = idx & 63, vf = idx >> 6;
            float4 cv = *(const float4*)(gC + ((size_t)b * NPIX + n0 + n) * CV + vc + vf*4);
            Cts[vf*4+0][n] = cv.x; Cts[vf*4+1][n] = cv.y;
            Cts[vf*4+2][n] = cv.z; Cts[vf*4+3][n] = cv.w;
        }
        __syncthreads();
#pragma unroll
        for (int v = 0; v < 32; v++) {
            float4 wv = *(const float4*)&Wst[v][ty*4];
            float4 cv = *(const float4*)&Cts[v][tx*4];
            acc[0][0]=fmaf(wv.x,cv.x,acc[0][0]); acc[0][1]=fmaf(wv.x,cv.y,acc[0][1]);
            acc[0][2]=fmaf(wv.x,cv.z,acc[0][2]); acc[0][3]=fmaf(wv.x,cv.w,acc[0][3]);
            acc[1][0]=fmaf(wv.y,cv.x,acc[1][0]); acc[1][1]=fmaf(wv.y,cv.y,acc[1][1]);
            acc[1][2]=fmaf(wv.y,cv.z,acc[1][2]); acc[1][3]=fmaf(wv.y,cv.w,acc[1][3]);
            acc[2][0]=fmaf(wv.z,cv.x,acc[2][0]); acc[2][1]=fmaf(wv.z,cv.y,acc[2][1]);
            acc[2][2]=fmaf(wv.z,cv.z,acc[2][2]); acc[2][3]=fmaf(wv.z,cv.w,acc[2][3]);
            acc[3][0]=fmaf(wv.w,cv.x,acc[3][0]); acc[3][1]=fmaf(wv.w,cv.y,acc[3][1]);
            acc[3][2]=fmaf(wv.w,cv.z,acc[3][2]); acc[3][3]=fmaf(wv.w,cv.w,acc[3][3]);
        }
        __syncthreads();
    }

    const float gm = gamma[0];
#pragma unroll
    for (int r = 0; r < 4; r++) {
        int o = o0 + ty*4 + r;
        float wb = Wb[o];
        size_t base = ((size_t)(b * CO + o)) * NPIX + n0 + tx*4;
        float4 xv = *(const float4*)(xin + base);
        float4 ov;
        ov.x = gm * (acc[r][0] + wb) + xv.x;
        ov.y = gm * (acc[r][1] + wb) + xv.y;
        ov.z = gm * (acc[r][2] + wb) + xv.z;
        ov.w = gm * (acc[r][3] + wb) + xv.w;
        *(float4*)(outp + base) = ov;
    }
}

// ---------------------------------------------------------------------------
extern "C" void kernel_launch(void* const* d_in, const int* in_sizes, int n_in,
                              void* d_out, int out_size)
{
    const float* x     = (const float*)d_in[0];
    const float* y     = (const float*)d_in[1];
    const float* fk_w  = (const float*)d_in[2];
    const float* fk_g  = (const float*)d_in[3];
    const float* fk_b  = (const float*)d_in[4];
    const float* fk_m  = (const float*)d_in[5];
    const float* fk_v  = (const float*)d_in[6];
    const float* fq_w  = (const float*)d_in[7];
    const float* fq_g  = (const float*)d_in[8];
    const float* fq_b  = (const float*)d_in[9];
    const float* fq_m  = (const float*)d_in[10];
    const float* fq_v  = (const float*)d_in[11];
    const float* fv_w  = (const float*)d_in[12];
    const float* fv_b  = (const float*)d_in[13];
    const float* W_w   = (const float*)d_in[14];
    const float* W_b   = (const float*)d_in[15];
    const float* gamma = (const float*)d_in[16];
    float* out = (float*)d_out;

    float *gQ, *gK, *gV, *gC;
    cudaGetSymbolAddress((void**)&gQ, g_Q);
    cudaGetSymbolAddress((void**)&gK, g_K);
    cudaGetSymbolAddress((void**)&gV, g_V);
    cudaGetSymbolAddress((void**)&gC, g_CTX);

    const int attn_smem = ATTN_SMEM_FLOATS * 4;   // 65792 B
    cudaFuncSetAttribute(attn_kernel,
                         cudaFuncAttributeMaxDynamicSharedMemorySize, attn_smem);

    dim3 pg(NPIX/64, BATCH);
    // k from x, q from y (with 1/sqrt(Ck) folded in), v from y
    proj_kernel<64, true ><<<pg, 256>>>(x, fk_w, fk_g, fk_b, fk_m, fk_v, gK, 1.0f);
    proj_kernel<64, true ><<<pg, 256>>>(y, fq_w, fq_g, fq_b, fq_m, fq_v, gQ, 0.125f);
    proj_kernel<128,false><<<pg, 256>>>(y, fv_w, nullptr, fv_b, nullptr, nullptr, gV, 1.0f);

    attn_kernel<<<dim3(NPIX/32, BATCH), 256, attn_smem>>>(gQ, gK, gV, gC);

    outproj_kernel<<<dim3(NPIX/64, CO/64, BATCH), 256>>>(W_w, W_b, x, gamma, gC, out);
}

// round 4
// speedup vs baseline: 8.5409x; 8.5409x over previous
#include <cuda_runtime.h>
#include <cuda_bf16.h>
#include <cstdint>
#include <math.h>

#define BATCH 2
#define CIN   256
#define NPIX  6400
#define CK    64
#define CV    128
#define CO    256
#define BM    64
#define BJ    128

// Scratch (device globals: allocation-free)
__device__ __nv_bfloat16 g_Q[BATCH*NPIX*CK];   // [b][n][ck] (pre-scaled by Ck^-0.5)
__device__ __nv_bfloat16 g_K[BATCH*NPIX*CK];   // [b][n][ck]
__device__ __nv_bfloat16 g_V[BATCH*CV*NPIX];   // [b][v][n]  channel-major
__device__ float         g_CTX[BATCH*NPIX*CV]; // [b][n][v]

// ======================= PTX helpers (all valid on compute_103) ============
__device__ __forceinline__ uint32_t smem_to_u32(const void* p) {
    uint32_t a;
    asm("{ .reg .u64 t; cvta.to.shared.u64 t, %1; cvt.u32.u64 %0, t; }" : "=r"(a) : "l"(p));
    return a;
}
#define CP_ASYNC16(dst, src) \
    asm volatile("cp.async.cg.shared.global [%0], [%1], 16;" :: "r"(dst), "l"(src))
#define CP_COMMIT() asm volatile("cp.async.commit_group;" ::: "memory")
#define CP_WAIT0()  asm volatile("cp.async.wait_group 0;" ::: "memory")

__device__ __forceinline__ void ldsm4(uint32_t* r, uint32_t addr) {
    asm volatile("ldmatrix.sync.aligned.m8n8.x4.shared.b16 {%0,%1,%2,%3}, [%4];"
        : "=r"(r[0]), "=r"(r[1]), "=r"(r[2]), "=r"(r[3]) : "r"(addr));
}
__device__ __forceinline__ void mma16816(float* c, const uint32_t* a,
                                         uint32_t b0, uint32_t b1) {
    asm volatile("mma.sync.aligned.m16n8k16.row.col.f32.bf16.bf16.f32 "
        "{%0,%1,%2,%3}, {%4,%5,%6,%7}, {%8,%9}, {%0,%1,%2,%3};"
        : "+f"(c[0]), "+f"(c[1]), "+f"(c[2]), "+f"(c[3])
        : "r"(a[0]), "r"(a[1]), "r"(a[2]), "r"(a[3]), "r"(b0), "r"(b1));
}
__device__ __forceinline__ uint32_t bf2u(float lo, float hi) {
    __nv_bfloat162 h = __float22bfloat162_rn(make_float2(lo, hi));
    return *reinterpret_cast<uint32_t*>(&h);
}

// XOR swizzles for conflict-free ldmatrix (16B-chunk index XOR row%8)
__device__ __forceinline__ uint32_t sw128(int row, int cb) {      // 128B rows
    return (uint32_t)(row * 128 + (cb ^ ((row & 7) << 4)));
}
__device__ __forceinline__ uint32_t sw256(int row, int cb) {      // 256B rows
    return (uint32_t)(row * 256 + (cb & 0x80) + ((cb & 0x7F) ^ ((row & 7) << 4)));
}

// SMEM layout (bytes): Q 64x64 bf16 (8KB) | K 128x64 (16KB) | V 128x128 (32KB)
#define SQ 0
#define SK 8192
#define SV 24576
#define ATTN_SMEM 57344

// ======================= mma.sync flash attention ==========================
__global__ __launch_bounds__(128, 2) void attn_mma(
    const __nv_bfloat16* __restrict__ gQ, const __nv_bfloat16* __restrict__ gK,
    const __nv_bfloat16* __restrict__ gV, float* __restrict__ gC)
{
    extern __shared__ char smem[];
    const uint32_t sb = smem_to_u32(smem);
    const int tid  = threadIdx.x;
    const int warp = tid >> 5, lane = tid & 31;
    const int n0   = blockIdx.x * BM;
    const int b    = blockIdx.y;

    // ---- Q tile -> smem -> register fragments (held all kernel) ----
    const __nv_bfloat16* qg = gQ + ((size_t)b * NPIX + n0) * CK;
    for (int idx = tid; idx < BM * CK / 8; idx += 128) {
        int row = idx >> 3, c16 = idx & 7;
        CP_ASYNC16(sb + SQ + sw128(row, c16 * 16), qg + (size_t)row * CK + c16 * 8);
    }
    CP_COMMIT(); CP_WAIT0();
    __syncthreads();

    uint32_t Qf[4][4];
    {
        int qrow = (warp << 4) + (lane & 15);
        int cbo  = (lane >= 16) ? 16 : 0;
#pragma unroll
        for (int kk = 0; kk < 4; kk++)
            ldsm4(Qf[kk], sb + SQ + sw128(qrow, kk * 32 + cbo));
    }

    const int g    = lane >> 3;
    const int jr   = ((g >> 1) << 3) + (lane & 7);  // row offset within 16-row group
    const int cbg  = (g & 1) << 4;                  // lo/hi 16B half

    float lsum0 = 0.f, lsum1 = 0.f;
    float O[16][4];
#pragma unroll
    for (int u = 0; u < 16; u++)
#pragma unroll
        for (int i = 0; i < 4; i++) O[u][i] = 0.f;

    for (int t = 0; t < NPIX / BJ; t++) {
        const int j0 = t * BJ;
        __syncthreads();                 // all warps done reading prev K/V
        const __nv_bfloat16* kg = gK + ((size_t)b * NPIX + j0) * CK;
        for (int idx = tid; idx < 1024; idx += 128) {
            int row = idx >> 3, c16 = idx & 7;
            CP_ASYNC16(sb + SK + sw128(row, c16 * 16), kg + (size_t)row * CK + c16 * 8);
        }
        const __nv_bfloat16* vg = gV + (size_t)b * CV * NPIX + j0;
        for (int idx = tid; idx < 2048; idx += 128) {
            int row = idx >> 4, c16 = idx & 15;
            CP_ASYNC16(sb + SV + sw256(row, c16 * 16), vg + (size_t)row * NPIX + c16 * 8);
        }
        CP_COMMIT(); CP_WAIT0();
        __syncthreads();

        // ---- GEMM1: S = Q K^T, fused exp + row-sum + pack to bf16 A-frags ----
        uint32_t Pf[8][4];
#pragma unroll
        for (int u = 0; u < 8; u++) {
            float c0[4] = {0, 0, 0, 0}, c1[4] = {0, 0, 0, 0};
#pragma unroll
            for (int kk = 0; kk < 4; kk++) {
                uint32_t kb[4];
                ldsm4(kb, sb + SK + sw128(u * 16 + jr, kk * 32 + cbg));
                mma16816(c0, Qf[kk], kb[0], kb[1]);
                mma16816(c1, Qf[kk], kb[2], kb[3]);
            }
#pragma unroll
            for (int i = 0; i < 4; i++) { c0[i] = __expf(c0[i]); c1[i] = __expf(c1[i]); }
            lsum0 += c0[0] + c0[1] + c1[0] + c1[1];
            lsum1 += c0[2] + c0[3] + c1[2] + c1[3];
            Pf[u][0] = bf2u(c0[0], c0[1]);
            Pf[u][1] = bf2u(c0[2], c0[3]);
            Pf[u][2] = bf2u(c1[0], c1[1]);
            Pf[u][3] = bf2u(c1[2], c1[3]);
        }

        // ---- GEMM2: O += P V^T ----
#pragma unroll
        for (int s = 0; s < 8; s++) {
#pragma unroll
            for (int u = 0; u < 8; u++) {
                uint32_t vb[4];
                ldsm4(vb, sb + SV + sw256(u * 16 + jr, s * 32 + cbg));
                mma16816(O[2 * u],     Pf[s], vb[0], vb[1]);
                mma16816(O[2 * u + 1], Pf[s], vb[2], vb[3]);
            }
        }
    }

    // ---- epilogue: normalize and store ----
    lsum0 += __shfl_xor_sync(0xffffffffu, lsum0, 1);
    lsum0 += __shfl_xor_sync(0xffffffffu, lsum0, 2);
    lsum1 += __shfl_xor_sync(0xffffffffu, lsum1, 1);
    lsum1 += __shfl_xor_sync(0xffffffffu, lsum1, 2);
    const float inv0 = 1.f / lsum0, inv1 = 1.f / lsum1;

    const int m = (warp << 4) + (lane >> 2);
    float* o0 = gC + ((size_t)b * NPIX + n0 + m) * CV;
    float* o1 = o0 + 8 * CV;
    const int vcol = 2 * (lane & 3);
#pragma unroll
    for (int u = 0; u < 16; u++) {
        int v = u * 8 + vcol;
        *(float2*)(o0 + v) = make_float2(O[u][0] * inv0, O[u][1] * inv0);
        *(float2*)(o1 + v) = make_float2(O[u][2] * inv1, O[u][3] * inv1);
    }
}

// ======================= projections (fp32 math, bf16 out) =================
template<int COP, bool BN, bool CHM>
__global__ __launch_bounds__(256) void proj_kernel(
    const float* __restrict__ xin, const float* __restrict__ w,
    const float* __restrict__ pg,  const float* __restrict__ pb,
    const float* __restrict__ pm,  const float* __restrict__ pv,
    __nv_bfloat16* __restrict__ outp, float outmul)
{
    constexpr int R = COP / 16;
    __shared__ float Xs[32][64];
    __shared__ float Wst[32][COP];
    const int n0  = blockIdx.x * 64;
    const int b   = blockIdx.y;
    const int tid = threadIdx.x;
    const int tx  = tid & 15, ty = tid >> 4;

    float acc[R][4];
#pragma unroll
    for (int r = 0; r < R; r++)
#pragma unroll
        for (int i = 0; i < 4; i++) acc[r][i] = 0.f;

    const float* xb = xin + (size_t)b * CIN * NPIX + n0;
    for (int cc = 0; cc < CIN; cc += 32) {
        for (int idx = tid; idx < 512; idx += 256) {
            int c = idx >> 4, nf = idx & 15;
            *(float4*)&Xs[c][nf*4] = *(const float4*)(xb + (size_t)(cc + c) * NPIX + nf*4);
        }
        for (int idx = tid; idx < COP*8; idx += 256) {
            int o = idx % COP, cf = idx / COP;
            float4 wv = *(const float4*)(w + (size_t)o * CIN + cc + cf*4);
            Wst[cf*4+0][o] = wv.x; Wst[cf*4+1][o] = wv.y;
            Wst[cf*4+2][o] = wv.z; Wst[cf*4+3][o] = wv.w;
        }
        __syncthreads();
#pragma unroll
        for (int c = 0; c < 32; c++) {
            float4 av = *(const float4*)&Xs[c][tx*4];
            float wr[R];
#pragma unroll
            for (int r = 0; r < R; r++) wr[r] = Wst[c][ty*R + r];
#pragma unroll
            for (int r = 0; r < R; r++) {
                acc[r][0] = fmaf(wr[r], av.x, acc[r][0]);
                acc[r][1] = fmaf(wr[r], av.y, acc[r][1]);
                acc[r][2] = fmaf(wr[r], av.z, acc[r][2]);
                acc[r][3] = fmaf(wr[r], av.w, acc[r][3]);
            }
        }
        __syncthreads();
    }

    float sc[R], b2[R];
#pragma unroll
    for (int r = 0; r < R; r++) {
        int o = ty*R + r;
        if constexpr (BN) {
            float s = pg[o] * rsqrtf(pv[o] + 1e-5f);
            sc[r] = s * outmul; b2[r] = (pb[o] - pm[o]*s) * outmul;
        } else {
            sc[r] = outmul; b2[r] = pb[o] * outmul;
        }
    }
    if constexpr (CHM) {
        // channel-major: out[(b*COP+o)*NPIX + n]
#pragma unroll
        for (int r = 0; r < R; r++) {
            int o = ty*R + r;
            uint2 u;
            u.x = bf2u(acc[r][0]*sc[r] + b2[r], acc[r][1]*sc[r] + b2[r]);
            u.y = bf2u(acc[r][2]*sc[r] + b2[r], acc[r][3]*sc[r] + b2[r]);
            *(uint2*)(outp + ((size_t)b * COP + o) * NPIX + n0 + tx*4) = u;
        }
    } else {
        // row-major: out[(b*NPIX+n)*COP + o], R==4
        __nv_bfloat16* ob = outp + ((size_t)b * NPIX + n0) * COP + ty*R;
#pragma unroll
        for (int i = 0; i < 4; i++) {
            uint2 u;
            u.x = bf2u(acc[0][i]*sc[0] + b2[0], acc[1][i]*sc[1] + b2[1]);
            u.y = bf2u(acc[2][i]*sc[2] + b2[2], acc[3][i]*sc[3] + b2[3]);
            *(uint2*)(ob + (size_t)(tx*4 + i) * COP) = u;
        }
    }
}

// ======================= output projection + residual ======================
__global__ __launch_bounds__(256) void outproj_kernel(
    const float* __restrict__ Ww, const float* __restrict__ Wb,
    const float* __restrict__ xin, const float* __restrict__ gamma,
    const float* __restrict__ gC, float* __restrict__ outp)
{
    __shared__ float Wst[32][64];
    __shared__ float Cts[32][64];
    const int n0 = blockIdx.x * 64;
    const int o0 = blockIdx.y * 64;
    const int b  = blockIdx.z;
    const int tid = threadIdx.x;
    const int tx  = tid & 15, ty = tid >> 4;

    float acc[4][4];
#pragma unroll
    for (int r = 0; r < 4; r++)
#pragma unroll
        for (int i = 0; i < 4; i++) acc[r][i] = 0.f;

    for (int vc = 0; vc < CV; vc += 32) {
        for (int idx = tid; idx < 512; idx += 256) {
            int o = idx & 63, vf = idx >> 6;
            float4 wv = *(const float4*)(Ww + (size_t)(o0 + o) * CV + vc + vf*4);
            Wst[vf*4+0][o] = wv.x; Wst[vf*4+1][o] = wv.y;
            Wst[vf*4+2][o] = wv.z; Wst[vf*4+3][o] = wv.w;
        }
        for (int idx = tid; idx < 512; idx += 256) {
            int n = idx & 63, vf = idx >> 6;
            float4 cv = *(const float4*)(gC + ((size_t)b * NPIX + n0 + n) * CV + vc + vf*4);
            Cts[vf*4+0][n] = cv.x; Cts[vf*4+1][n] = cv.y;
            Cts[vf*4+2][n] = cv.z; Cts[vf*4+3][n] = cv.w;
        }
        __syncthreads();
#pragma unroll
        for (int v = 0; v < 32; v++) {
            float4 wv = *(const float4*)&Wst[v][ty*4];
            float4 cv = *(const float4*)&Cts[v][tx*4];
            acc[0][0]=fmaf(wv.x,cv.x,acc[0][0]); acc[0][1]=fmaf(wv.x,cv.y,acc[0][1]);
            acc[0][2]=fmaf(wv.x,cv.z,acc[0][2]); acc[0][3]=fmaf(wv.x,cv.w,acc[0][3]);
            acc[1][0]=fmaf(wv.y,cv.x,acc[1][0]); acc[1][1]=fmaf(wv.y,cv.y,acc[1][1]);
            acc[1][2]=fmaf(wv.y,cv.z,acc[1][2]); acc[1][3]=fmaf(wv.y,cv.w,acc[1][3]);
            acc[2][0]=fmaf(wv.z,cv.x,acc[2][0]); acc[2][1]=fmaf(wv.z,cv.y,acc[2][1]);
            acc[2][2]=fmaf(wv.z,cv.z,acc[2][2]); acc[2][3]=fmaf(wv.z,cv.w,acc[2][3]);
            acc[3][0]=fmaf(wv.w,cv.x,acc[3][0]); acc[3][1]=fmaf(wv.w,cv.y,acc[3][1]);
            acc[3][2]=fmaf(wv.w,cv.z,acc[3][2]); acc[3][3]=fmaf(wv.w,cv.w,acc[3][3]);
        }
        __syncthreads();
    }

    const float gm = gamma[0];
#pragma unroll
    for (int r = 0; r < 4; r++) {
        int o = o0 + ty*4 + r;
        float wb = Wb[o];
        size_t base = ((size_t)(b * CO + o)) * NPIX + n0 + tx*4;
        float4 xv = *(const float4*)(xin + base);
        float4 ov;
        ov.x = gm * (acc[r][0] + wb) + xv.x;
        ov.y = gm * (acc[r][1] + wb) + xv.y;
        ov.z = gm * (acc[r][2] + wb) + xv.z;
        ov.w = gm * (acc[r][3] + wb) + xv.w;
        *(float4*)(outp + base) = ov;
    }
}

// ---------------------------------------------------------------------------
extern "C" void kernel_launch(void* const* d_in, const int* in_sizes, int n_in,
                              void* d_out, int out_size)
{
    const float* x     = (const float*)d_in[0];
    const float* y     = (const float*)d_in[1];
    const float* fk_w  = (const float*)d_in[2];
    const float* fk_g  = (const float*)d_in[3];
    const float* fk_b  = (const float*)d_in[4];
    const float* fk_m  = (const float*)d_in[5];
    const float* fk_v  = (const float*)d_in[6];
    const float* fq_w  = (const float*)d_in[7];
    const float* fq_g  = (const float*)d_in[8];
    const float* fq_b  = (const float*)d_in[9];
    const float* fq_m  = (const float*)d_in[10];
    const float* fq_v  = (const float*)d_in[11];
    const float* fv_w  = (const float*)d_in[12];
    const float* fv_b  = (const float*)d_in[13];
    const float* W_w   = (const float*)d_in[14];
    const float* W_b   = (const float*)d_in[15];
    const float* gamma = (const float*)d_in[16];
    float* out = (float*)d_out;

    __nv_bfloat16 *gQ, *gK, *gV;
    float *gC;
    cudaGetSymbolAddress((void**)&gQ, g_Q);
    cudaGetSymbolAddress((void**)&gK, g_K);
    cudaGetSymbolAddress((void**)&gV, g_V);
    cudaGetSymbolAddress((void**)&gC, g_CTX);

    cudaFuncSetAttribute(attn_mma, cudaFuncAttributeMaxDynamicSharedMemorySize, ATTN_SMEM);

    dim3 pg(NPIX/64, BATCH);
    // k from x, q from y (1/sqrt(Ck) folded into q), v from y (channel-major)
    proj_kernel<64,  true,  false><<<pg, 256>>>(x, fk_w, fk_g, fk_b, fk_m, fk_v, gK, 1.0f);
    proj_kernel<64,  true,  false><<<pg, 256>>>(y, fq_w, fq_g, fq_b, fq_m, fq_v, gQ, 0.125f);
    proj_kernel<128, false, true ><<<pg, 256>>>(y, fv_w, nullptr, fv_b, nullptr, nullptr, gV, 1.0f);

    attn_mma<<<dim3(NPIX/BM, BATCH), 128, ATTN_SMEM>>>(gQ, gK, gV, gC);

    outproj_kernel<<<dim3(NPIX/64, CO/64, BATCH), 256>>>(W_w, W_b, x, gamma, gC, out);
}

// round 8
// speedup vs baseline: 11.5691x; 1.3546x over previous
#include <cuda_runtime.h>
#include <cuda_bf16.h>
#include <cstdint>
#include <math.h>

#define BATCH 2
#define CIN   256
#define NPIX  6400
#define CK    64
#define CV    128
#define CO    256
#define BM    64
#define BJ    128
#define NT    (NPIX/BJ)

// Scratch (device globals: allocation-free)
__device__ __nv_bfloat16 g_Xt[BATCH*NPIX*CIN];  // [b][n][c] bf16 (x transposed)
__device__ __nv_bfloat16 g_Yt[BATCH*NPIX*CIN];  // [b][n][c] bf16 (y transposed)
__device__ __nv_bfloat16 g_Q[BATCH*NPIX*CK];    // [b][n][ck] (pre-scaled by Ck^-0.5)
__device__ __nv_bfloat16 g_K[BATCH*NPIX*CK];    // [b][n][ck]
__device__ __nv_bfloat16 g_V[BATCH*CV*NPIX];    // [b][v][n] channel-major
__device__ __nv_bfloat16 g_CTX[BATCH*NPIX*CV];  // [b][n][v]

// ======================= PTX helpers (compute_103-safe) ====================
__device__ __forceinline__ uint32_t smem_to_u32(const void* p) {
    uint32_t a;
    asm("{ .reg .u64 t; cvta.to.shared.u64 t, %1; cvt.u32.u64 %0, t; }" : "=r"(a) : "l"(p));
    return a;
}
#define CP_ASYNC16(dst, src) \
    asm volatile("cp.async.cg.shared.global [%0], [%1], 16;" :: "r"(dst), "l"(src))
#define CP_COMMIT() asm volatile("cp.async.commit_group;" ::: "memory")
#define CP_WAIT0()  asm volatile("cp.async.wait_group 0;" ::: "memory")
#define CP_WAIT1()  asm volatile("cp.async.wait_group 1;" ::: "memory")

__device__ __forceinline__ void ldsm4(uint32_t* r, uint32_t addr) {
    asm volatile("ldmatrix.sync.aligned.m8n8.x4.shared.b16 {%0,%1,%2,%3}, [%4];"
        : "=r"(r[0]), "=r"(r[1]), "=r"(r[2]), "=r"(r[3]) : "r"(addr));
}
__device__ __forceinline__ void mma16816(float* c, const uint32_t* a,
                                         uint32_t b0, uint32_t b1) {
    asm volatile("mma.sync.aligned.m16n8k16.row.col.f32.bf16.bf16.f32 "
        "{%0,%1,%2,%3}, {%4,%5,%6,%7}, {%8,%9}, {%0,%1,%2,%3};"
        : "+f"(c[0]), "+f"(c[1]), "+f"(c[2]), "+f"(c[3])
        : "r"(a[0]), "r"(a[1]), "r"(a[2]), "r"(a[3]), "r"(b0), "r"(b1));
}
__device__ __forceinline__ uint32_t bf2u(float lo, float hi) {
    __nv_bfloat162 h = __float22bfloat162_rn(make_float2(lo, hi));
    return *reinterpret_cast<uint32_t*>(&h);
}

// XOR swizzles for conflict-free ldmatrix (16B chunk index XOR row%8)
__device__ __forceinline__ uint32_t sw128(int row, int cb) {   // 128B rows
    return (uint32_t)(row * 128 + (cb ^ ((row & 7) << 4)));
}
__device__ __forceinline__ uint32_t sw256(int row, int cb) {   // 256B rows
    return (uint32_t)(row * 256 + (cb & ~127) + ((cb & 127) ^ ((row & 7) << 4)));
}
__device__ __forceinline__ uint32_t sw512(int row, int cb) {   // 512B rows
    return (uint32_t)(row * 512 + (cb & ~127) + ((cb & 127) ^ ((row & 7) << 4)));
}

// ======================= transpose + fp32->bf16 ============================
// in [b][c][n] fp32 -> out [b][n][c] bf16
__global__ __launch_bounds__(256) void transpose_bf16(
    const float* __restrict__ in, __nv_bfloat16* __restrict__ out)
{
    __shared__ float s[32][33];
    const int n0 = blockIdx.x * 32, c0 = blockIdx.y * 32, b = blockIdx.z;
    const int tid = threadIdx.x;
#pragma unroll
    for (int i = 0; i < 4; i++) {
        int c = (tid >> 5) + i * 8, n = tid & 31;
        s[c][n] = in[((size_t)(b * CIN) + c0 + c) * NPIX + n0 + n];
    }
    __syncthreads();
#pragma unroll
    for (int i = 0; i < 2; i++) {
        int n = (tid >> 4) + i * 16, cp = tid & 15;
        uint32_t u = bf2u(s[2 * cp][n], s[2 * cp + 1][n]);
        *(uint32_t*)(out + ((size_t)(b * NPIX) + n0 + n) * CIN + c0 + 2 * cp) = u;
    }
}

// ======================= Q/K projection (tensor core) ======================
// out[b][n][o] bf16 = (xt[n][:] . w[o][:]) * sc[o] + b2[o]   (M=128n,N=64o,K=256)
__global__ __launch_bounds__(128, 2) void qk_proj(
    const __nv_bfloat16* __restrict__ xt, const float* __restrict__ w,
    const float* __restrict__ pg, const float* __restrict__ pb,
    const float* __restrict__ pm, const float* __restrict__ pv,
    __nv_bfloat16* __restrict__ gout, float outmul)
{
    extern __shared__ char smem[];
    const uint32_t sb = smem_to_u32(smem);
    const uint32_t SW = 0, SA = 32768;
    float* ssc = (float*)(smem + 49152);
    float* sb2 = (float*)(smem + 49408);
    const int tid = threadIdx.x, warp = tid >> 5, lane = tid & 31;
    const int n0 = blockIdx.x * 128, b = blockIdx.y;
    const int g = lane >> 3, jr = ((g >> 1) << 3) + (lane & 7), cbg = (g & 1) << 4;
    const int cbo = (lane >= 16) ? 16 : 0;

    // W fp32 -> bf16 swizzled smem [64][256]
    for (int idx = tid; idx < 64 * 128; idx += 128) {
        int o = idx >> 7, cp = idx & 127;
        float2 wv = *(const float2*)(w + (size_t)o * 256 + cp * 2);
        *(uint32_t*)(smem + SW + sw512(o, cp * 4)) = bf2u(wv.x, wv.y);
    }
    if (tid < 64) {
        float s = pg[tid] * rsqrtf(pv[tid] + 1e-5f);
        ssc[tid] = s * outmul;
        sb2[tid] = (pb[tid] - pm[tid] * s) * outmul;
    }

    float C[2][8][4];
#pragma unroll
    for (int u = 0; u < 2; u++)
#pragma unroll
        for (int j = 0; j < 8; j++)
#pragma unroll
            for (int i = 0; i < 4; i++) C[u][j][i] = 0.f;

    for (int kc = 0; kc < 4; kc++) {
        __syncthreads();
        // A chunk: xt rows [128 n][64 c] bf16
        for (int idx = tid; idx < 1024; idx += 128) {
            int row = idx >> 3, c16 = idx & 7;
            CP_ASYNC16(sb + SA + sw128(row, c16 * 16),
                       xt + ((size_t)(b * NPIX) + n0 + row) * CIN + kc * 64 + c16 * 8);
        }
        CP_COMMIT(); CP_WAIT0();
        __syncthreads();
#pragma unroll
        for (int kk = 0; kk < 4; kk++) {
            uint32_t Af[2][4];
#pragma unroll
            for (int u = 0; u < 2; u++)
                ldsm4(Af[u], sb + SA + sw128(warp * 32 + u * 16 + (lane & 15), kk * 32 + cbo));
#pragma unroll
            for (int jb = 0; jb < 4; jb++) {
                uint32_t Bf[4];
                ldsm4(Bf, sb + SW + sw512(jb * 16 + jr, kc * 128 + kk * 32 + cbg));
#pragma unroll
                for (int u = 0; u < 2; u++) {
                    mma16816(C[u][2 * jb],     Af[u], Bf[0], Bf[1]);
                    mma16816(C[u][2 * jb + 1], Af[u], Bf[2], Bf[3]);
                }
            }
        }
    }
    __syncthreads();

#pragma unroll
    for (int u = 0; u < 2; u++)
#pragma unroll
        for (int j = 0; j < 8; j++)
#pragma unroll
            for (int h = 0; h < 2; h++) {
                int m = warp * 32 + u * 16 + (lane >> 2) + h * 8;
                int o = j * 8 + 2 * (lane & 3);
                float a = C[u][j][2 * h]     * ssc[o]     + sb2[o];
                float c = C[u][j][2 * h + 1] * ssc[o + 1] + sb2[o + 1];
                *(uint32_t*)(gout + ((size_t)(b * NPIX) + n0 + m) * CK + o) = bf2u(a, c);
            }
}

// ======================= V projection (tensor core) ========================
// out[b][v][n] bf16 = w[v][:] . yt[n][:] + bias[v]   (M=128v,N=128n,K=256)
__global__ __launch_bounds__(128, 2) void v_proj(
    const __nv_bfloat16* __restrict__ yt, const float* __restrict__ w,
    const float* __restrict__ bias, __nv_bfloat16* __restrict__ gout)
{
    extern __shared__ char smem[];
    const uint32_t sb = smem_to_u32(smem);
    const uint32_t SW = 0, SB = 65536;
    const int tid = threadIdx.x, warp = tid >> 5, lane = tid & 31;
    const int n0 = blockIdx.x * 128, b = blockIdx.y;
    const int g = lane >> 3, jr = ((g >> 1) << 3) + (lane & 7), cbg = (g & 1) << 4;
    const int cbo = (lane >= 16) ? 16 : 0;

    for (int idx = tid; idx < 128 * 128; idx += 128) {
        int o = idx >> 7, cp = idx & 127;
        float2 wv = *(const float2*)(w + (size_t)o * 256 + cp * 2);
        *(uint32_t*)(smem + SW + sw512(o, cp * 4)) = bf2u(wv.x, wv.y);
    }

    float C[2][16][4];
#pragma unroll
    for (int u = 0; u < 2; u++)
#pragma unroll
        for (int j = 0; j < 16; j++)
#pragma unroll
            for (int i = 0; i < 4; i++) C[u][j][i] = 0.f;

    for (int kc = 0; kc < 4; kc++) {
        __syncthreads();
        for (int idx = tid; idx < 1024; idx += 128) {
            int row = idx >> 3, c16 = idx & 7;
            CP_ASYNC16(sb + SB + sw128(row, c16 * 16),
                       yt + ((size_t)(b * NPIX) + n0 + row) * CIN + kc * 64 + c16 * 8);
        }
        CP_COMMIT(); CP_WAIT0();
        __syncthreads();
#pragma unroll
        for (int kk = 0; kk < 4; kk++) {
            uint32_t Af[2][4];
#pragma unroll
            for (int u = 0; u < 2; u++)
                ldsm4(Af[u], sb + SW + sw512(warp * 32 + u * 16 + (lane & 15),
                                             kc * 128 + kk * 32 + cbo));
#pragma unroll
            for (int jb = 0; jb < 8; jb++) {
                uint32_t Bf[4];
                ldsm4(Bf, sb + SB + sw128(jb * 16 + jr, kk * 32 + cbg));
#pragma unroll
                for (int u = 0; u < 2; u++) {
                    mma16816(C[u][2 * jb],     Af[u], Bf[0], Bf[1]);
                    mma16816(C[u][2 * jb + 1], Af[u], Bf[2], Bf[3]);
                }
            }
        }
    }
    __syncthreads();

#pragma unroll
    for (int u = 0; u < 2; u++)
#pragma unroll
        for (int h = 0; h < 2; h++) {
            int v = warp * 32 + u * 16 + (lane >> 2) + h * 8;
            float bv = __ldg(bias + v);
#pragma unroll
            for (int j = 0; j < 16; j++) {
                int n = j * 8 + 2 * (lane & 3);
                *(uint32_t*)(gout + ((size_t)(b * CV) + v) * NPIX + n0 + n) =
                    bf2u(C[u][j][2 * h] + bv, C[u][j][2 * h + 1] + bv);
            }
        }
}

// ======================= mma.sync flash attention (2-stage pipe) ===========
#define SQ 0
#define STG_STRIDE 49152
#define SK_OF(s) (8192 + (s) * STG_STRIDE)
#define SV_OF(s) (24576 + (s) * STG_STRIDE)
#define ATTN_SMEM (8192 + 2 * STG_STRIDE)   // 106496

__global__ __launch_bounds__(128, 2) void attn_mma(
    const __nv_bfloat16* __restrict__ gQ, const __nv_bfloat16* __restrict__ gK,
    const __nv_bfloat16* __restrict__ gV, __nv_bfloat16* __restrict__ gC)
{
    extern __shared__ char smem[];
    const uint32_t sb = smem_to_u32(smem);
    const int tid  = threadIdx.x;
    const int warp = tid >> 5, lane = tid & 31;
    const int n0   = blockIdx.x * BM;
    const int b    = blockIdx.y;

    // Q tile -> smem -> register fragments
    const __nv_bfloat16* qg = gQ + ((size_t)b * NPIX + n0) * CK;
    for (int idx = tid; idx < BM * CK / 8; idx += 128) {
        int row = idx >> 3, c16 = idx & 7;
        CP_ASYNC16(sb + SQ + sw128(row, c16 * 16), qg + (size_t)row * CK + c16 * 8);
    }
    CP_COMMIT(); CP_WAIT0();
    __syncthreads();

    uint32_t Qf[4][4];
    {
        int qrow = (warp << 4) + (lane & 15);
        int cbo  = (lane >= 16) ? 16 : 0;
#pragma unroll
        for (int kk = 0; kk < 4; kk++)
            ldsm4(Qf[kk], sb + SQ + sw128(qrow, kk * 32 + cbo));
    }

    const int g   = lane >> 3;
    const int jr  = ((g >> 1) << 3) + (lane & 7);
    const int cbg = (g & 1) << 4;

    const __nv_bfloat16* kbase = gK + (size_t)b * NPIX * CK;
    const __nv_bfloat16* vbase = gV + (size_t)b * CV * NPIX;

    // preload tile 0 into stage 0
    {
        const __nv_bfloat16* kg = kbase;
        for (int idx = tid; idx < 1024; idx += 128) {
            int row = idx >> 3, c16 = idx & 7;
            CP_ASYNC16(sb + SK_OF(0) + sw128(row, c16 * 16), kg + (size_t)row * CK + c16 * 8);
        }
        const __nv_bfloat16* vg = vbase;
        for (int idx = tid; idx < 2048; idx += 128) {
            int row = idx >> 4, c16 = idx & 15;
            CP_ASYNC16(sb + SV_OF(0) + sw256(row, c16 * 16), vg + (size_t)row * NPIX + c16 * 8);
        }
        CP_COMMIT();
    }

    float lsum0 = 0.f, lsum1 = 0.f;
    float O[16][4];
#pragma unroll
    for (int u = 0; u < 16; u++)
#pragma unroll
        for (int i = 0; i < 4; i++) O[u][i] = 0.f;

    for (int t = 0; t < NT; t++) {
        const int st = t & 1;
        if (t + 1 < NT) {   // prefetch next tile into other stage
            const int sn = (t + 1) & 1;
            const __nv_bfloat16* kg = kbase + (size_t)(t + 1) * BJ * CK;
            for (int idx = tid; idx < 1024; idx += 128) {
                int row = idx >> 3, c16 = idx & 7;
                CP_ASYNC16(sb + SK_OF(sn) + sw128(row, c16 * 16), kg + (size_t)row * CK + c16 * 8);
            }
            const __nv_bfloat16* vg = vbase + (t + 1) * BJ;
            for (int idx = tid; idx < 2048; idx += 128) {
                int row = idx >> 4, c16 = idx & 15;
                CP_ASYNC16(sb + SV_OF(sn) + sw256(row, c16 * 16), vg + (size_t)row * NPIX + c16 * 8);
            }
            CP_COMMIT(); CP_WAIT1();
        } else {
            CP_WAIT0();
        }
        __syncthreads();

        // GEMM1: S = Q K^T, fused exp + row-sum + pack bf16 A-frags
        uint32_t Pf[8][4];
#pragma unroll
        for (int u = 0; u < 8; u++) {
            float c0[4] = {0, 0, 0, 0}, c1[4] = {0, 0, 0, 0};
#pragma unroll
            for (int kk = 0; kk < 4; kk++) {
                uint32_t kb[4];
                ldsm4(kb, sb + SK_OF(st) + sw128(u * 16 + jr, kk * 32 + cbg));
                mma16816(c0, Qf[kk], kb[0], kb[1]);
                mma16816(c1, Qf[kk], kb[2], kb[3]);
            }
#pragma unroll
            for (int i = 0; i < 4; i++) { c0[i] = __expf(c0[i]); c1[i] = __expf(c1[i]); }
            lsum0 += c0[0] + c0[1] + c1[0] + c1[1];
            lsum1 += c0[2] + c0[3] + c1[2] + c1[3];
            Pf[u][0] = bf2u(c0[0], c0[1]);
            Pf[u][1] = bf2u(c0[2], c0[3]);
            Pf[u][2] = bf2u(c1[0], c1[1]);
            Pf[u][3] = bf2u(c1[2], c1[3]);
        }

        // GEMM2: O += P V^T
#pragma unroll
        for (int s = 0; s < 8; s++) {
#pragma unroll
            for (int u = 0; u < 8; u++) {
                uint32_t vb[4];
                ldsm4(vb, sb + SV_OF(st) + sw256(u * 16 + jr, s * 32 + cbg));
                mma16816(O[2 * u],     Pf[s], vb[0], vb[1]);
                mma16816(O[2 * u + 1], Pf[s], vb[2], vb[3]);
            }
        }
        __syncthreads();
    }

    // epilogue: normalize and store bf16 ctx [n][v]
    lsum0 += __shfl_xor_sync(0xffffffffu, lsum0, 1);
    lsum0 += __shfl_xor_sync(0xffffffffu, lsum0, 2);
    lsum1 += __shfl_xor_sync(0xffffffffu, lsum1, 1);
    lsum1 += __shfl_xor_sync(0xffffffffu, lsum1, 2);
    const float inv0 = 1.f / lsum0, inv1 = 1.f / lsum1;

    const int m = (warp << 4) + (lane >> 2);
    __nv_bfloat16* o0 = gC + ((size_t)b * NPIX + n0 + m) * CV;
    __nv_bfloat16* o1 = o0 + 8 * CV;
    const int vcol = 2 * (lane & 3);
#pragma unroll
    for (int u = 0; u < 16; u++) {
        int v = u * 8 + vcol;
        *(uint32_t*)(o0 + v) = bf2u(O[u][0] * inv0, O[u][1] * inv0);
        *(uint32_t*)(o1 + v) = bf2u(O[u][2] * inv1, O[u][3] * inv1);
    }
}

// ======================= output projection + residual ======================
// out[b][o][n] f32 = gamma*(Ww[o][:].ctx[n][:] + Wb[o]) + x[b][o][n]
// M=256 o, N=64 n, K=128 v
__global__ __launch_bounds__(128, 2) void outproj_mma(
    const float* __restrict__ Ww, const float* __restrict__ Wb,
    const float* __restrict__ xin, const float* __restrict__ gamma,
    const __nv_bfloat16* __restrict__ gC, float* __restrict__ outp)
{
    extern __shared__ char smem[];
    const uint32_t sb = smem_to_u32(smem);
    const uint32_t SW = 0, SB = 65536;
    const int tid = threadIdx.x, warp = tid >> 5, lane = tid & 31;
    const int n0 = blockIdx.x * 64, b = blockIdx.y;
    const int g = lane >> 3, jr = ((g >> 1) << 3) + (lane & 7), cbg = (g & 1) << 4;
    const int cbo = (lane >= 16) ? 16 : 0;

    // Ww fp32 -> bf16 swizzled smem [256][128]
    for (int idx = tid; idx < 256 * 64; idx += 128) {
        int o = idx >> 6, vp = idx & 63;
        float2 wv = *(const float2*)(Ww + (size_t)o * CV + vp * 2);
        *(uint32_t*)(smem + SW + sw256(o, vp * 4)) = bf2u(wv.x, wv.y);
    }
    // ctx tile [64 n][128 v] bf16
    for (int idx = tid; idx < 1024; idx += 128) {
        int row = idx >> 4, c16 = idx & 15;
        CP_ASYNC16(sb + SB + sw256(row, c16 * 16),
                   gC + ((size_t)(b * NPIX) + n0 + row) * CV + c16 * 8);
    }
    CP_COMMIT(); CP_WAIT0();
    __syncthreads();

    float C[4][8][4];
#pragma unroll
    for (int u = 0; u < 4; u++)
#pragma unroll
        for (int j = 0; j < 8; j++)
#pragma unroll
            for (int i = 0; i < 4; i++) C[u][j][i] = 0.f;

#pragma unroll
    for (int kk = 0; kk < 8; kk++) {
        uint32_t Af[4][4];
#pragma unroll
        for (int u = 0; u < 4; u++)
            ldsm4(Af[u], sb + SW + sw256(warp * 64 + u * 16 + (lane & 15), kk * 32 + cbo));
#pragma unroll
        for (int jb = 0; jb < 4; jb++) {
            uint32_t Bf[4];
            ldsm4(Bf, sb + SB + sw256(jb * 16 + jr, kk * 32 + cbg));
#pragma unroll
            for (int u = 0; u < 4; u++) {
                mma16816(C[u][2 * jb],     Af[u], Bf[0], Bf[1]);
                mma16816(C[u][2 * jb + 1], Af[u], Bf[2], Bf[3]);
            }
        }
    }

    const float gm = __ldg(gamma);
#pragma unroll
    for (int u = 0; u < 4; u++)
#pragma unroll
        for (int h = 0; h < 2; h++) {
            int o = warp * 64 + u * 16 + (lane >> 2) + h * 8;
            float wb = __ldg(Wb + o);
#pragma unroll
            for (int j = 0; j < 8; j++) {
                int n = n0 + j * 8 + 2 * (lane & 3);
                size_t base = ((size_t)(b * CO + o)) * NPIX + n;
                float2 xv = *(const float2*)(xin + base);
                float2 ov;
                ov.x = gm * (C[u][j][2 * h]     + wb) + xv.x;
                ov.y = gm * (C[u][j][2 * h + 1] + wb) + xv.y;
                *(float2*)(outp + base) = ov;
            }
        }
}

// ---------------------------------------------------------------------------
extern "C" void kernel_launch(void* const* d_in, const int* in_sizes, int n_in,
                              void* d_out, int out_size)
{
    const float* x     = (const float*)d_in[0];
    const float* y     = (const float*)d_in[1];
    const float* fk_w  = (const float*)d_in[2];
    const float* fk_g  = (const float*)d_in[3];
    const float* fk_b  = (const float*)d_in[4];
    const float* fk_m  = (const float*)d_in[5];
    const float* fk_v  = (const float*)d_in[6];
    const float* fq_w  = (const float*)d_in[7];
    const float* fq_g  = (const float*)d_in[8];
    const float* fq_b  = (const float*)d_in[9];
    const float* fq_m  = (const float*)d_in[10];
    const float* fq_v  = (const float*)d_in[11];
    const float* fv_w  = (const float*)d_in[12];
    const float* fv_b  = (const float*)d_in[13];
    const float* W_w   = (const float*)d_in[14];
    const float* W_b   = (const float*)d_in[15];
    const float* gamma = (const float*)d_in[16];
    float* out = (float*)d_out;

    __nv_bfloat16 *gXt, *gYt, *gQ, *gK, *gV, *gC;
    cudaGetSymbolAddress((void**)&gXt, g_Xt);
    cudaGetSymbolAddress((void**)&gYt, g_Yt);
    cudaGetSymbolAddress((void**)&gQ, g_Q);
    cudaGetSymbolAddress((void**)&gK, g_K);
    cudaGetSymbolAddress((void**)&gV, g_V);
    cudaGetSymbolAddress((void**)&gC, g_CTX);

    static bool attr_done = false;
    if (!attr_done) {
        cudaFuncSetAttribute(attn_mma,   cudaFuncAttributeMaxDynamicSharedMemorySize, ATTN_SMEM);
        cudaFuncSetAttribute(qk_proj,    cudaFuncAttributeMaxDynamicSharedMemorySize, 49664);
        cudaFuncSetAttribute(v_proj,     cudaFuncAttributeMaxDynamicSharedMemorySize, 81920);
        cudaFuncSetAttribute(outproj_mma,cudaFuncAttributeMaxDynamicSharedMemorySize, 81920);
        attr_done = true;
    }

    dim3 tg(NPIX / 32, CIN / 32, BATCH);
    transpose_bf16<<<tg, 256>>>(x, gXt);
    transpose_bf16<<<tg, 256>>>(y, gYt);

    dim3 pgq(NPIX / 128, BATCH);
    qk_proj<<<pgq, 128, 49664>>>(gXt, fk_w, fk_g, fk_b, fk_m, fk_v, gK, 1.0f);
    qk_proj<<<pgq, 128, 49664>>>(gYt, fq_w, fq_g, fq_b, fq_m, fq_v, gQ, 0.125f);
    v_proj <<<pgq, 128, 81920>>>(gYt, fv_w, fv_b, gV);

    attn_mma<<<dim3(NPIX / BM, BATCH), 128, ATTN_SMEM>>>(gQ, gK, gV, gC);

    outproj_mma<<<dim3(NPIX / 64, BATCH), 128, 81920>>>(W_w, W_b, x, gamma, gC, out);
}